// round 1
// baseline (speedup 1.0000x reference)
#include <cuda_runtime.h>
#include <math.h>

#define N 4096
#define D 4096
#define BM 128
#define BN 128
#define BK 16

// Scratch (device globals: no allocations allowed)
__device__ float g_sq[N];     // row squared norms
__device__ float g_std[N];    // per-row std (ddof=1)
__device__ float g_xent[N];   // per-row cross-entropy
__device__ float g_ap[N];     // hardest-positive distance
__device__ int   g_an2[N];    // min dist^2 to diff-identity (float bits, atomicMin-able since >0)

// ---------------------------------------------------------------------------
// Kernel 1: per-row stats: sq norm, std (ddof=1), cross-entropy (stable LSE).
// Also initializes g_an2 to +inf.
// ---------------------------------------------------------------------------
__global__ void row_stats_kernel(const float* __restrict__ x, const int* __restrict__ tgt) {
    const int row = blockIdx.x;
    const int tid = threadIdx.x;                 // 256 threads
    const float* xr = x + (size_t)row * D;

    float s = 0.f, ss = 0.f, mx = -INFINITY;
    #pragma unroll 4
    for (int k = tid; k < D; k += 256) {
        float v = xr[k];
        s += v;
        ss = fmaf(v, v, ss);
        mx = fmaxf(mx, v);
    }
    __shared__ float sh_s[256], sh_ss[256], sh_m[256];
    sh_s[tid] = s; sh_ss[tid] = ss; sh_m[tid] = mx;
    __syncthreads();
    for (int off = 128; off > 0; off >>= 1) {
        if (tid < off) {
            sh_s[tid]  += sh_s[tid + off];
            sh_ss[tid] += sh_ss[tid + off];
            sh_m[tid]   = fmaxf(sh_m[tid], sh_m[tid + off]);
        }
        __syncthreads();
    }
    const float rowmax = sh_m[0];

    float se = 0.f;
    #pragma unroll 4
    for (int k = tid; k < D; k += 256) {
        se += __expf(xr[k] - rowmax);
    }
    __shared__ float sh_e[256];
    sh_e[tid] = se;
    __syncthreads();
    for (int off = 128; off > 0; off >>= 1) {
        if (tid < off) sh_e[tid] += sh_e[tid + off];
        __syncthreads();
    }

    if (tid == 0) {
        float sum = sh_s[0], sumsq = sh_ss[0];
        g_sq[row] = sumsq;
        float var = (sumsq - sum * sum / (float)D) / (float)(D - 1);
        g_std[row] = sqrtf(fmaxf(var, 0.f));
        float lse = rowmax + logf(sh_e[0]);
        g_xent[row] = lse - xr[tgt[row]];
        g_an2[row] = 0x7f800000;                 // +inf bits
    }
}

// ---------------------------------------------------------------------------
// Kernel 2: hardest positive per row. Groups = 4 consecutive rows (same id).
// 6 intra-group dot products per block, then dist_ap via max.
// ---------------------------------------------------------------------------
__global__ void group_ap_kernel(const float* __restrict__ x) {
    const int g = blockIdx.x;
    const int tid = threadIdx.x;                 // 128 threads
    const float* r = x + (size_t)(4 * g) * D;

    float d01 = 0.f, d02 = 0.f, d03 = 0.f, d12 = 0.f, d13 = 0.f, d23 = 0.f;
    for (int k = tid; k < D; k += 128) {
        float a = r[k], b = r[k + D], c = r[k + 2 * D], e = r[k + 3 * D];
        d01 = fmaf(a, b, d01); d02 = fmaf(a, c, d02); d03 = fmaf(a, e, d03);
        d12 = fmaf(b, c, d12); d13 = fmaf(b, e, d13); d23 = fmaf(c, e, d23);
    }
    __shared__ float sh[6][128];
    sh[0][tid] = d01; sh[1][tid] = d02; sh[2][tid] = d03;
    sh[3][tid] = d12; sh[4][tid] = d13; sh[5][tid] = d23;
    __syncthreads();
    for (int off = 64; off > 0; off >>= 1) {
        if (tid < off) {
            #pragma unroll
            for (int q = 0; q < 6; q++) sh[q][tid] += sh[q][tid + off];
        }
        __syncthreads();
    }
    if (tid < 4) {
        const int a = tid;
        float sqv[4];
        #pragma unroll
        for (int q = 0; q < 4; q++) sqv[q] = g_sq[4 * g + q];
        float dot[4][4];
        dot[0][1] = dot[1][0] = sh[0][0];
        dot[0][2] = dot[2][0] = sh[1][0];
        dot[0][3] = dot[3][0] = sh[2][0];
        dot[1][2] = dot[2][1] = sh[3][0];
        dot[1][3] = dot[3][1] = sh[4][0];
        dot[2][3] = dot[3][2] = sh[5][0];
        float ap = 1e-6f;                        // self distance = sqrt(1e-12)
        #pragma unroll
        for (int b = 0; b < 4; b++) {
            if (b != a) {
                float d2 = fmaxf(sqv[a] + sqv[b] - 2.f * dot[a][b], 1e-12f);
                ap = fmaxf(ap, sqrtf(d2));
            }
        }
        g_ap[4 * g + a] = ap;
    }
}

// ---------------------------------------------------------------------------
// Kernel 3: fused Gram GEMM + hardest-negative min reduction.
// C[i][j] = x_i . x_j ; dist2 = sq_i + sq_j - 2C ; min over diff-identity j.
// 128x128 tile, 8x8 micro-tile, fp32. Deterministic atomicMin on float bits.
// ---------------------------------------------------------------------------
__global__ void __launch_bounds__(256)
gemm_min_kernel(const float* __restrict__ x, const int* __restrict__ tgt) {
    __shared__ float As[BK][BM];
    __shared__ float Bs[BK][BN];
    const int bi = blockIdx.y * BM;
    const int bj = blockIdx.x * BN;
    const int tid = threadIdx.x;
    const int tx = tid & 15;                     // 0..15 -> cols
    const int ty = tid >> 4;                     // 0..15 -> rows

    float acc[8][8];
    #pragma unroll
    for (int m = 0; m < 8; m++)
        #pragma unroll
        for (int n = 0; n < 8; n++) acc[m][n] = 0.f;

    const int lr = tid >> 2;                     // 0..63 (row within half-tile)
    const int lc = (tid & 3) * 4;                // 0,4,8,12 (k offset)

    for (int k0 = 0; k0 < D; k0 += BK) {
        #pragma unroll
        for (int l = 0; l < 2; l++) {
            int r = lr + l * 64;
            float4 va = *(const float4*)(x + (size_t)(bi + r) * D + k0 + lc);
            As[lc + 0][r] = va.x; As[lc + 1][r] = va.y;
            As[lc + 2][r] = va.z; As[lc + 3][r] = va.w;
            float4 vb = *(const float4*)(x + (size_t)(bj + r) * D + k0 + lc);
            Bs[lc + 0][r] = vb.x; Bs[lc + 1][r] = vb.y;
            Bs[lc + 2][r] = vb.z; Bs[lc + 3][r] = vb.w;
        }
        __syncthreads();
        #pragma unroll
        for (int k = 0; k < BK; k++) {
            float a[8], b[8];
            *(float4*)&a[0] = *(const float4*)&As[k][ty * 8];
            *(float4*)&a[4] = *(const float4*)&As[k][ty * 8 + 4];
            *(float4*)&b[0] = *(const float4*)&Bs[k][tx * 8];
            *(float4*)&b[4] = *(const float4*)&Bs[k][tx * 8 + 4];
            #pragma unroll
            for (int m = 0; m < 8; m++)
                #pragma unroll
                for (int n = 0; n < 8; n++)
                    acc[m][n] = fmaf(a[m], b[n], acc[m][n]);
        }
        __syncthreads();
    }

    // Epilogue: dist2 + same-identity mask + min over j within tile.
    float sqi[8], sqj[8];
    int ti_[8], tj_[8];
    #pragma unroll
    for (int m = 0; m < 8; m++) { int i = bi + ty * 8 + m; sqi[m] = g_sq[i]; ti_[m] = tgt[i]; }
    #pragma unroll
    for (int n = 0; n < 8; n++) { int j = bj + tx * 8 + n; sqj[n] = g_sq[j]; tj_[n] = tgt[j]; }

    #pragma unroll
    for (int m = 0; m < 8; m++) {
        float rmin = INFINITY;
        #pragma unroll
        for (int n = 0; n < 8; n++) {
            float d2 = fmaxf(fmaf(-2.f, acc[m][n], sqi[m] + sqj[n]), 1e-12f);
            if (ti_[m] != tj_[n]) rmin = fminf(rmin, d2);
        }
        // reduce across the 16 tx lanes (contiguous half-warp)
        #pragma unroll
        for (int off = 8; off > 0; off >>= 1)
            rmin = fminf(rmin, __shfl_xor_sync(0xffffffffu, rmin, off));
        if (tx == 0)
            atomicMin(&g_an2[bi + ty * 8 + m], __float_as_int(rmin));
    }
}

// ---------------------------------------------------------------------------
// Kernel 4: deterministic final reduction -> loss, prec.
// ---------------------------------------------------------------------------
__global__ void finalize_kernel(float* __restrict__ out, int out_size) {
    const int tid = threadIdx.x;                 // 1024 threads
    float trip = 0.f, prec = 0.f, stds = 0.f, xents = 0.f;
    for (int i = tid; i < N; i += 1024) {
        float ap = g_ap[i];
        float an = sqrtf(__int_as_float(g_an2[i]));
        trip += fmaxf(ap - an, 0.f);             // MARGIN = 0
        if (an > ap) prec += 1.f;
        stds  += g_std[i];
        xents += g_xent[i];
    }
    __shared__ float s1[1024], s2[1024], s3[1024], s4[1024];
    s1[tid] = trip; s2[tid] = prec; s3[tid] = stds; s4[tid] = xents;
    __syncthreads();
    for (int off = 512; off > 0; off >>= 1) {
        if (tid < off) {
            s1[tid] += s1[tid + off];
            s2[tid] += s2[tid + off];
            s3[tid] += s3[tid + off];
            s4[tid] += s4[tid + off];
        }
        __syncthreads();
    }
    if (tid == 0) {
        float loss = (s1[0] / (float)N)          // ALPHA=1.0 * mean triplet
                   + 0.5f * s3[0]                // BETA=0.5  * sum std
                   + 0.5f * (s4[0] / (float)N);  // GAMMA=0.5 * mean xent
        if (out_size >= 1) out[0] = loss;
        if (out_size >= 2) out[1] = s2[0] / (float)N;
    }
}

extern "C" void kernel_launch(void* const* d_in, const int* in_sizes, int n_in,
                              void* d_out, int out_size) {
    const float* x   = (const float*)d_in[0];
    const int*   tgt = (const int*)d_in[1];

    row_stats_kernel<<<N, 256>>>(x, tgt);
    group_ap_kernel<<<N / 4, 128>>>(x);
    dim3 grid(N / BN, N / BM);
    gemm_min_kernel<<<grid, 256>>>(x, tgt);
    finalize_kernel<<<1, 1024>>>((float*)d_out, out_size);
}

// round 4
// speedup vs baseline: 4.3306x; 4.3306x over previous
#include <cuda_runtime.h>
#include <cuda_bf16.h>
#include <math.h>
#include <stdint.h>

#define N 4096
#define D 4096

// ---------------- scratch globals (no allocations allowed) -----------------
__device__ float g_sq[N];
__device__ float g_std[N];
__device__ float g_xent[N];
__device__ float g_ap[N];
__device__ int   g_an2[N];
__device__ __nv_bfloat16 g_xhi[(size_t)N * D];
__device__ __nv_bfloat16 g_xlo[(size_t)N * D];

// ---------------- PTX helpers ----------------------------------------------
__device__ __forceinline__ uint32_t smem_u32(const void* p) {
    uint32_t a;
    asm("{ .reg .u64 t; cvta.to.shared.u64 t, %1; cvt.u32.u64 %0, t; }" : "=r"(a) : "l"(p));
    return a;
}
#define CP16(so, gp) asm volatile("cp.async.cg.shared.global [%0], [%1], 16;" :: "r"(so), "l"(gp) : "memory")
#define CP_COMMIT()  asm volatile("cp.async.commit_group;" ::: "memory")

__device__ __forceinline__ void ldsm4(uint32_t* r, uint32_t p) {
    asm volatile("ldmatrix.sync.aligned.m8n8.x4.shared.b16 {%0,%1,%2,%3}, [%4];"
                 : "=r"(r[0]), "=r"(r[1]), "=r"(r[2]), "=r"(r[3]) : "r"(p));
}
__device__ __forceinline__ void mma16816(float* d, const uint32_t* a, const uint32_t* b) {
    asm volatile("mma.sync.aligned.m16n8k16.row.col.f32.bf16.bf16.f32 "
                 "{%0,%1,%2,%3},{%4,%5,%6,%7},{%8,%9},{%0,%1,%2,%3};"
                 : "+f"(d[0]), "+f"(d[1]), "+f"(d[2]), "+f"(d[3])
                 : "r"(a[0]), "r"(a[1]), "r"(a[2]), "r"(a[3]), "r"(b[0]), "r"(b[1]));
}

// ---------------- kernel 1: row stats + hi/lo bf16 split -------------------
__global__ void row_stats_kernel(const float* __restrict__ x, const int* __restrict__ tgt) {
    const int row = blockIdx.x;
    const int tid = threadIdx.x;                 // 256
    const float* xr = x + (size_t)row * D;
    __nv_bfloat16* __restrict__ xh = g_xhi + (size_t)row * D;
    __nv_bfloat16* __restrict__ xl = g_xlo + (size_t)row * D;

    float s = 0.f, ss = 0.f, mx = -INFINITY;
    for (int k = tid; k < D; k += 256) {
        float v = xr[k];
        s += v; ss = fmaf(v, v, ss); mx = fmaxf(mx, v);
        __nv_bfloat16 h = __float2bfloat16(v);
        __nv_bfloat16 l = __float2bfloat16(v - __bfloat162float(h));
        xh[k] = h; xl[k] = l;
    }
    __shared__ float sh_s[256], sh_ss[256], sh_m[256];
    sh_s[tid] = s; sh_ss[tid] = ss; sh_m[tid] = mx;
    __syncthreads();
    for (int off = 128; off > 0; off >>= 1) {
        if (tid < off) {
            sh_s[tid] += sh_s[tid + off];
            sh_ss[tid] += sh_ss[tid + off];
            sh_m[tid] = fmaxf(sh_m[tid], sh_m[tid + off]);
        }
        __syncthreads();
    }
    const float rowmax = sh_m[0];
    float se = 0.f;
    for (int k = tid; k < D; k += 256) se += __expf(xr[k] - rowmax);
    __shared__ float sh_e[256];
    sh_e[tid] = se;
    __syncthreads();
    for (int off = 128; off > 0; off >>= 1) {
        if (tid < off) sh_e[tid] += sh_e[tid + off];
        __syncthreads();
    }
    if (tid == 0) {
        float sum = sh_s[0], sumsq = sh_ss[0];
        g_sq[row] = sumsq;
        float var = (sumsq - sum * sum / (float)D) / (float)(D - 1);
        g_std[row] = sqrtf(fmaxf(var, 0.f));
        g_xent[row] = rowmax + logf(sh_e[0]) - xr[tgt[row]];
        g_an2[row] = 0x7f800000;
    }
}

// ---------------- kernel 2: hardest positive (groups of 4) -----------------
__global__ void group_ap_kernel(const float* __restrict__ x) {
    const int g = blockIdx.x;
    const int tid = threadIdx.x;                 // 128
    const float* r = x + (size_t)(4 * g) * D;
    float d01 = 0.f, d02 = 0.f, d03 = 0.f, d12 = 0.f, d13 = 0.f, d23 = 0.f;
    for (int k = tid; k < D; k += 128) {
        float a = r[k], b = r[k + D], c = r[k + 2 * D], e = r[k + 3 * D];
        d01 = fmaf(a, b, d01); d02 = fmaf(a, c, d02); d03 = fmaf(a, e, d03);
        d12 = fmaf(b, c, d12); d13 = fmaf(b, e, d13); d23 = fmaf(c, e, d23);
    }
    __shared__ float sh[6][128];
    sh[0][tid] = d01; sh[1][tid] = d02; sh[2][tid] = d03;
    sh[3][tid] = d12; sh[4][tid] = d13; sh[5][tid] = d23;
    __syncthreads();
    for (int off = 64; off > 0; off >>= 1) {
        if (tid < off) {
            #pragma unroll
            for (int q = 0; q < 6; q++) sh[q][tid] += sh[q][tid + off];
        }
        __syncthreads();
    }
    if (tid < 4) {
        const int a = tid;
        float sqv[4];
        #pragma unroll
        for (int q = 0; q < 4; q++) sqv[q] = g_sq[4 * g + q];
        float dot[4][4];
        dot[0][1] = dot[1][0] = sh[0][0];
        dot[0][2] = dot[2][0] = sh[1][0];
        dot[0][3] = dot[3][0] = sh[2][0];
        dot[1][2] = dot[2][1] = sh[3][0];
        dot[1][3] = dot[3][1] = sh[4][0];
        dot[2][3] = dot[3][2] = sh[5][0];
        float ap = 1e-6f;
        #pragma unroll
        for (int b = 0; b < 4; b++) {
            if (b != a) {
                float d2 = fmaxf(sqv[a] + sqv[b] - 2.f * dot[a][b], 1e-12f);
                ap = fmaxf(ap, sqrtf(d2));
            }
        }
        g_ap[4 * g + a] = ap;
    }
}

// ---------------- kernel 3: mma.sync split-bf16 Gram + min mining ----------
// Tile 128(A-rows) x 256(B-rows), supra-diagonal only. 8 warps, warp 64x64.
#define KC    32
#define RSTRB 80                    // bytes per smem row (64B data + 16B pad)
#define A_HI  0
#define A_LO  10240
#define B_HI  20480
#define B_LO  40960
#define STG   61440
#define SMEM_TOTAL (2 * STG)

struct TilePos { int bi, bj; };
__device__ __forceinline__ TilePos tile_pos(int t) {
    int rb = 0;
    for (;;) { int cnt = 16 - (rb >> 1); if (t < cnt) break; t -= cnt; rb++; }
    return { rb * 128, ((rb >> 1) + t) * 256 };
}

__device__ __forceinline__ void load_chunk(uint32_t su, int bi, int bj, int c, int lr, int lu) {
    const size_t kof = ((size_t)c << 5) + ((size_t)lu << 3);
    #pragma unroll
    for (int p = 0; p < 2; p++) {
        int r = lr + 64 * p;
        size_t go = ((size_t)(bi + r) << 12) + kof;
        uint32_t so = su + r * RSTRB + lu * 16;
        CP16(so + A_HI, g_xhi + go);
        CP16(so + A_LO, g_xlo + go);
    }
    #pragma unroll
    for (int p = 0; p < 4; p++) {
        int r = lr + 64 * p;
        size_t go = ((size_t)(bj + r) << 12) + kof;
        uint32_t so = su + B_HI + r * RSTRB + lu * 16;
        CP16(so, g_xhi + go);
        CP16(so + (B_LO - B_HI), g_xlo + go);
    }
    CP_COMMIT();
}

__global__ void __launch_bounds__(256, 1)
gemm_min_mma(const int* __restrict__ tgt) {
    extern __shared__ char smem[];
    const uint32_t sb = smem_u32(smem);
    const int tid = threadIdx.x, wid = tid >> 5, lane = tid & 31;
    TilePos tp = tile_pos(blockIdx.x);
    const int bi = tp.bi, bj = tp.bj;
    const int wr = wid >> 2, wc = wid & 3;       // warp grid 2x4
    const int m0 = wr * 64, n0 = wc * 64;

    float acc[4][8][4];
    #pragma unroll
    for (int a = 0; a < 4; a++)
        #pragma unroll
        for (int b = 0; b < 8; b++)
            #pragma unroll
            for (int q = 0; q < 4; q++) acc[a][b][q] = 0.f;

    const int lr = tid >> 2, lu = tid & 3;
    load_chunk(sb, bi, bj, 0, lr, lu);
    load_chunk(sb + STG, bi, bj, 1, lr, lu);

    // per-thread ldmatrix byte offsets (within stage)
    const uint32_t a_base = (uint32_t)(m0 + (lane & 15)) * RSTRB + (((lane >> 4) << 3) << 1);
    const uint32_t b_base = B_HI + (uint32_t)(n0 + (lane & 7) + ((lane >> 4) << 3)) * RSTRB
                          + ((((lane >> 3) & 1) << 3) << 1);

    for (int c = 0; c < 128; c++) {
        const uint32_t su = sb + (c & 1) * STG;
        if (c < 127) asm volatile("cp.async.wait_group 1;" ::: "memory");
        else         asm volatile("cp.async.wait_group 0;" ::: "memory");
        __syncthreads();

        #pragma unroll
        for (int kk = 0; kk < 2; kk++) {         // two k16 steps per chunk
            const uint32_t ko = kk * 32;         // 16 elems * 2B
            uint32_t ah[4][4], al[4][4];
            #pragma unroll
            for (int mb = 0; mb < 4; mb++) {
                uint32_t ap_ = su + a_base + ko + mb * 16 * RSTRB;
                ldsm4(ah[mb], ap_);
                ldsm4(al[mb], ap_ + A_LO);
            }
            #pragma unroll
            for (int g = 0; g < 4; g++) {        // 16-col groups (2 n8 blocks each)
                uint32_t bp = su + b_base + ko + g * 16 * RSTRB;
                uint32_t bh[4], bl[4];
                ldsm4(bh, bp);
                ldsm4(bl, bp + (B_LO - B_HI));
                #pragma unroll
                for (int mb = 0; mb < 4; mb++) {
                    mma16816(acc[mb][2 * g],     ah[mb], bh);
                    mma16816(acc[mb][2 * g],     ah[mb], bl);
                    mma16816(acc[mb][2 * g],     al[mb], bh);
                    mma16816(acc[mb][2 * g + 1], ah[mb], bh + 2);
                    mma16816(acc[mb][2 * g + 1], ah[mb], bl + 2);
                    mma16816(acc[mb][2 * g + 1], al[mb], bh + 2);
                }
            }
        }
        __syncthreads();
        if (c + 2 < 128) load_chunk(su, bi, bj, c + 2, lr, lu);
    }
    __syncthreads();

    // ---- epilogue: d2 + mask, row & col mins --------------------------------
    float* s_sqi = (float*)(smem);               // 128 floats
    float* s_sqj = (float*)(smem + 512);         // 256 floats
    int*   s_ti  = (int*)(smem + 1536);          // 128 ints
    int*   s_tj  = (int*)(smem + 2048);          // 256 ints
    int*   s_row = (int*)(smem + 3072);          // 128 ints
    int*   s_col = (int*)(smem + 3584);          // 256 ints
    if (tid < 128) {
        s_sqi[tid] = g_sq[bi + tid];
        s_ti[tid]  = tgt[bi + tid];
        s_row[tid] = 0x7f800000;
    }
    s_sqj[tid] = g_sq[bj + tid];
    s_tj[tid]  = tgt[bj + tid];
    s_col[tid] = 0x7f800000;
    __syncthreads();

    const int g4 = lane >> 2, i2 = lane & 3;
    float sqj_r[16]; int tj_r[16];
    #pragma unroll
    for (int h = 0; h < 2; h++)
        #pragma unroll
        for (int nb = 0; nb < 4; nb++)
            #pragma unroll
            for (int e = 0; e < 2; e++) {
                int col = n0 + 32 * h + 8 * nb + 2 * i2 + e;
                sqj_r[(h * 4 + nb) * 2 + e] = s_sqj[col];
                tj_r[(h * 4 + nb) * 2 + e]  = s_tj[col];
            }

    // convert acc -> d2 in place
    #pragma unroll
    for (int mb = 0; mb < 4; mb++) {
        #pragma unroll
        for (int rh = 0; rh < 2; rh++) {
            int row = m0 + 16 * mb + g4 + 8 * rh;
            float sqi = s_sqi[row];
            int   ti  = s_ti[row];
            #pragma unroll
            for (int blk = 0; blk < 8; blk++)
                #pragma unroll
                for (int e = 0; e < 2; e++) {
                    int q = rh * 2 + e;
                    float d2 = fmaf(-2.f, acc[mb][blk][q], sqi + sqj_r[blk * 2 + e]);
                    d2 = fmaxf(d2, 1e-12f);
                    if (ti == tj_r[blk * 2 + e]) d2 = __int_as_float(0x7f800000);
                    acc[mb][blk][q] = d2;
                }
        }
    }
    // row mins (reduce over the 4 lanes sharing a row: shfl 1,2)
    #pragma unroll
    for (int mb = 0; mb < 4; mb++)
        #pragma unroll
        for (int rh = 0; rh < 2; rh++) {
            float rm = __int_as_float(0x7f800000);
            #pragma unroll
            for (int blk = 0; blk < 8; blk++)
                #pragma unroll
                for (int e = 0; e < 2; e++) rm = fminf(rm, acc[mb][blk][rh * 2 + e]);
            rm = fminf(rm, __shfl_xor_sync(0xffffffffu, rm, 1));
            rm = fminf(rm, __shfl_xor_sync(0xffffffffu, rm, 2));
            if (i2 == 0) atomicMin(&s_row[m0 + 16 * mb + g4 + 8 * rh], __float_as_int(rm));
        }
    // col mins (reduce over the 8 lanes sharing columns: shfl 4,8,16)
    #pragma unroll
    for (int blk = 0; blk < 8; blk++)
        #pragma unroll
        for (int e = 0; e < 2; e++) {
            float cm = __int_as_float(0x7f800000);
            #pragma unroll
            for (int mb = 0; mb < 4; mb++)
                #pragma unroll
                for (int q = 0; q < 4; q += 2) cm = fminf(cm, acc[mb][blk][q + e]);
            cm = fminf(cm, __shfl_xor_sync(0xffffffffu, cm, 4));
            cm = fminf(cm, __shfl_xor_sync(0xffffffffu, cm, 8));
            cm = fminf(cm, __shfl_xor_sync(0xffffffffu, cm, 16));
            if (g4 == 0) atomicMin(&s_col[n0 + 8 * blk + 2 * i2 + e], __float_as_int(cm));
        }
    __syncthreads();
    if (tid < 128) atomicMin(&g_an2[bi + tid], s_row[tid]);
    atomicMin(&g_an2[bj + tid], s_col[tid]);
}

// ---------------- kernel 4: deterministic finalize -------------------------
__global__ void finalize_kernel(float* __restrict__ out, int out_size) {
    const int tid = threadIdx.x;                 // 1024
    float trip = 0.f, prec = 0.f, stds = 0.f, xents = 0.f;
    for (int i = tid; i < N; i += 1024) {
        float ap = g_ap[i];
        float an = sqrtf(__int_as_float(g_an2[i]));
        trip += fmaxf(ap - an, 0.f);
        if (an > ap) prec += 1.f;
        stds += g_std[i];
        xents += g_xent[i];
    }
    __shared__ float s1[1024], s2[1024], s3[1024], s4[1024];
    s1[tid] = trip; s2[tid] = prec; s3[tid] = stds; s4[tid] = xents;
    __syncthreads();
    for (int off = 512; off > 0; off >>= 1) {
        if (tid < off) {
            s1[tid] += s1[tid + off]; s2[tid] += s2[tid + off];
            s3[tid] += s3[tid + off]; s4[tid] += s4[tid + off];
        }
        __syncthreads();
    }
    if (tid == 0) {
        float loss = (s1[0] / (float)N) + 0.5f * s3[0] + 0.5f * (s4[0] / (float)N);
        if (out_size >= 1) out[0] = loss;
        if (out_size >= 2) out[1] = s2[0] / (float)N;
    }
}

extern "C" void kernel_launch(void* const* d_in, const int* in_sizes, int n_in,
                              void* d_out, int out_size) {
    const float* x   = (const float*)d_in[0];
    const int*   tgt = (const int*)d_in[1];

    cudaFuncSetAttribute(gemm_min_mma, cudaFuncAttributeMaxDynamicSharedMemorySize, SMEM_TOTAL);

    row_stats_kernel<<<N, 256>>>(x, tgt);
    group_ap_kernel<<<N / 4, 128>>>(x);
    gemm_min_mma<<<272, 256, SMEM_TOTAL>>>(tgt);
    finalize_kernel<<<1, 1024>>>((float*)d_out, out_size);
}

// round 5
// speedup vs baseline: 7.9905x; 1.8451x over previous
#include <cuda_runtime.h>
#include <cuda_bf16.h>
#include <math.h>
#include <stdint.h>

#define N 4096
#define D 4096

// ---------------- scratch globals (no allocations allowed) -----------------
__device__ float g_sq[N];
__device__ float g_std[N];
__device__ float g_xent[N];
__device__ float g_ap[N];
__device__ int   g_anA[N];                    // approx min dist^2 (float bits)
__device__ float g_an2f[N];                   // exact min dist^2
__device__ __nv_bfloat16 g_xhi[(size_t)N * D];
__device__ float g_dist2[(size_t)N * N];      // approx dist^2 matrix (64MB)

// ---------------- PTX helpers ----------------------------------------------
__device__ __forceinline__ uint32_t smem_u32(const void* p) {
    uint32_t a;
    asm("{ .reg .u64 t; cvta.to.shared.u64 t, %1; cvt.u32.u64 %0, t; }" : "=r"(a) : "l"(p));
    return a;
}
#define CP16(so, gp) asm volatile("cp.async.cg.shared.global [%0], [%1], 16;" :: "r"(so), "l"(gp) : "memory")
#define CP_COMMIT()  asm volatile("cp.async.commit_group;" ::: "memory")

__device__ __forceinline__ void ldsm4(uint32_t* r, uint32_t p) {
    asm volatile("ldmatrix.sync.aligned.m8n8.x4.shared.b16 {%0,%1,%2,%3}, [%4];"
                 : "=r"(r[0]), "=r"(r[1]), "=r"(r[2]), "=r"(r[3]) : "r"(p));
}
__device__ __forceinline__ void mma16816(float* d, const uint32_t* a, const uint32_t* b) {
    asm volatile("mma.sync.aligned.m16n8k16.row.col.f32.bf16.bf16.f32 "
                 "{%0,%1,%2,%3},{%4,%5,%6,%7},{%8,%9},{%0,%1,%2,%3};"
                 : "+f"(d[0]), "+f"(d[1]), "+f"(d[2]), "+f"(d[3])
                 : "r"(a[0]), "r"(a[1]), "r"(a[2]), "r"(a[3]), "r"(b[0]), "r"(b[1]));
}

// ---------------- kernel 1: row stats + hi bf16 -----------------------------
__global__ void row_stats_kernel(const float* __restrict__ x, const int* __restrict__ tgt) {
    const int row = blockIdx.x;
    const int tid = threadIdx.x;                 // 256
    const float* xr = x + (size_t)row * D;
    __nv_bfloat16* __restrict__ xh = g_xhi + (size_t)row * D;

    float s = 0.f, ss = 0.f, mx = -INFINITY;
    for (int k = tid; k < D; k += 256) {
        float v = xr[k];
        s += v; ss = fmaf(v, v, ss); mx = fmaxf(mx, v);
        xh[k] = __float2bfloat16(v);
    }
    __shared__ float sh_s[256], sh_ss[256], sh_m[256];
    sh_s[tid] = s; sh_ss[tid] = ss; sh_m[tid] = mx;
    __syncthreads();
    for (int off = 128; off > 0; off >>= 1) {
        if (tid < off) {
            sh_s[tid] += sh_s[tid + off];
            sh_ss[tid] += sh_ss[tid + off];
            sh_m[tid] = fmaxf(sh_m[tid], sh_m[tid + off]);
        }
        __syncthreads();
    }
    const float rowmax = sh_m[0];
    float se = 0.f;
    for (int k = tid; k < D; k += 256) se += __expf(xr[k] - rowmax);
    __shared__ float sh_e[256];
    sh_e[tid] = se;
    __syncthreads();
    for (int off = 128; off > 0; off >>= 1) {
        if (tid < off) sh_e[tid] += sh_e[tid + off];
        __syncthreads();
    }
    if (tid == 0) {
        float sum = sh_s[0], sumsq = sh_ss[0];
        g_sq[row] = sumsq;
        float var = (sumsq - sum * sum / (float)D) / (float)(D - 1);
        g_std[row] = sqrtf(fmaxf(var, 0.f));
        g_xent[row] = rowmax + logf(sh_e[0]) - xr[tgt[row]];
        g_anA[row] = 0x7f800000;
    }
}

// ---------------- kernel 2: hardest positive (groups of 4) -----------------
__global__ void group_ap_kernel(const float* __restrict__ x) {
    const int g = blockIdx.x;
    const int tid = threadIdx.x;                 // 128
    const float* r = x + (size_t)(4 * g) * D;
    float d01 = 0.f, d02 = 0.f, d03 = 0.f, d12 = 0.f, d13 = 0.f, d23 = 0.f;
    for (int k = tid; k < D; k += 128) {
        float a = r[k], b = r[k + D], c = r[k + 2 * D], e = r[k + 3 * D];
        d01 = fmaf(a, b, d01); d02 = fmaf(a, c, d02); d03 = fmaf(a, e, d03);
        d12 = fmaf(b, c, d12); d13 = fmaf(b, e, d13); d23 = fmaf(c, e, d23);
    }
    __shared__ float sh[6][128];
    sh[0][tid] = d01; sh[1][tid] = d02; sh[2][tid] = d03;
    sh[3][tid] = d12; sh[4][tid] = d13; sh[5][tid] = d23;
    __syncthreads();
    for (int off = 64; off > 0; off >>= 1) {
        if (tid < off) {
            #pragma unroll
            for (int q = 0; q < 6; q++) sh[q][tid] += sh[q][tid + off];
        }
        __syncthreads();
    }
    if (tid < 4) {
        const int a = tid;
        float sqv[4];
        #pragma unroll
        for (int q = 0; q < 4; q++) sqv[q] = g_sq[4 * g + q];
        float dot[4][4];
        dot[0][1] = dot[1][0] = sh[0][0];
        dot[0][2] = dot[2][0] = sh[1][0];
        dot[0][3] = dot[3][0] = sh[2][0];
        dot[1][2] = dot[2][1] = sh[3][0];
        dot[1][3] = dot[3][1] = sh[4][0];
        dot[2][3] = dot[3][2] = sh[5][0];
        float ap = 1e-6f;
        #pragma unroll
        for (int b = 0; b < 4; b++) {
            if (b != a) {
                float d2 = fmaxf(sqv[a] + sqv[b] - 2.f * dot[a][b], 1e-12f);
                ap = fmaxf(ap, sqrtf(d2));
            }
        }
        g_ap[4 * g + a] = ap;
    }
}

// ---------------- kernel 3: hi-only bf16 Gram + store + min mining ---------
// Tile 128(A) x 256(B), supra-diagonal only. 8 warps (2x4), warp 64x64.
#define RSTRB 80                     // 64B data + 16B pad
#define A_HI  0
#define B_HI  10240
#define STG   30720
#define NSTG  4
#define SMEM_TOTAL (NSTG * STG)

struct TilePos { int bi, bj; };
__device__ __forceinline__ TilePos tile_pos(int t) {
    int rb = 0;
    for (;;) { int cnt = 16 - (rb >> 1); if (t < cnt) break; t -= cnt; rb++; }
    return { rb * 128, ((rb >> 1) + t) * 256 };
}

__device__ __forceinline__ void load_chunk(uint32_t su, int bi, int bj, int c, int lr2, int lu2) {
    // 256 threads load 384 rows x 64B: thread -> (row = tid>>1 grows by 128), 32B each
    const size_t kof = ((size_t)c << 5) + ((size_t)lu2 << 4);
    #pragma unroll
    for (int p = 0; p < 1; p++) {
        int r = lr2;                              // 0..127
        size_t go = ((size_t)(bi + r) << 12) + kof;
        uint32_t so = su + A_HI + r * RSTRB + lu2 * 32;
        CP16(so, g_xhi + go);
        CP16(so + 16, g_xhi + go + 8);
    }
    #pragma unroll
    for (int p = 0; p < 2; p++) {
        int r = lr2 + 128 * p;
        size_t go = ((size_t)(bj + r) << 12) + kof;
        uint32_t so = su + B_HI + r * RSTRB + lu2 * 32;
        CP16(so, g_xhi + go);
        CP16(so + 16, g_xhi + go + 8);
    }
    CP_COMMIT();
}

__global__ void __launch_bounds__(256, 1)
gemm_min_mma(const int* __restrict__ tgt) {
    extern __shared__ char smem[];
    const uint32_t sb = smem_u32(smem);
    const int tid = threadIdx.x, wid = tid >> 5, lane = tid & 31;
    TilePos tp = tile_pos(blockIdx.x);
    const int bi = tp.bi, bj = tp.bj;
    const int wr = wid >> 2, wc = wid & 3;
    const int m0 = wr * 64, n0 = wc * 64;

    float acc[4][8][4];
    #pragma unroll
    for (int a = 0; a < 4; a++)
        #pragma unroll
        for (int b = 0; b < 8; b++)
            #pragma unroll
            for (int q = 0; q < 4; q++) acc[a][b][q] = 0.f;

    const int lr2 = tid >> 1, lu2 = tid & 1;
    load_chunk(sb + 0 * STG, bi, bj, 0, lr2, lu2);
    load_chunk(sb + 1 * STG, bi, bj, 1, lr2, lu2);
    load_chunk(sb + 2 * STG, bi, bj, 2, lr2, lu2);

    const uint32_t a_base = A_HI + (uint32_t)(m0 + (lane & 15)) * RSTRB + (((lane >> 4) << 3) << 1);
    const uint32_t b_base = B_HI + (uint32_t)(n0 + (lane & 7) + ((lane >> 4) << 3)) * RSTRB
                          + ((((lane >> 3) & 1) << 3) << 1);

    for (int c = 0; c < 128; c++) {
        const uint32_t su = sb + (c & (NSTG - 1)) * STG;
        if (c < 126) asm volatile("cp.async.wait_group 2;" ::: "memory");
        else if (c == 126) asm volatile("cp.async.wait_group 1;" ::: "memory");
        else asm volatile("cp.async.wait_group 0;" ::: "memory");
        __syncthreads();

        #pragma unroll
        for (int kk = 0; kk < 2; kk++) {
            const uint32_t ko = kk * 32;
            uint32_t ah[4][4];
            #pragma unroll
            for (int mb = 0; mb < 4; mb++) ldsm4(ah[mb], su + a_base + ko + mb * 16 * RSTRB);
            #pragma unroll
            for (int g = 0; g < 4; g++) {
                uint32_t bh[4];
                ldsm4(bh, su + b_base + ko + g * 16 * RSTRB);
                #pragma unroll
                for (int mb = 0; mb < 4; mb++) {
                    mma16816(acc[mb][2 * g],     ah[mb], bh);
                    mma16816(acc[mb][2 * g + 1], ah[mb], bh + 2);
                }
            }
        }
        if (c + 3 < 128) load_chunk(sb + ((c + 3) & (NSTG - 1)) * STG, bi, bj, c + 3, lr2, lu2);
    }
    __syncthreads();

    // ---- epilogue: d2 + mask, store matrix (+transpose), row & col mins ----
    float* s_sqi = (float*)(smem);               // 128 floats
    float* s_sqj = (float*)(smem + 512);         // 256 floats
    int*   s_ti  = (int*)(smem + 1536);          // 128 ints
    int*   s_tj  = (int*)(smem + 2048);          // 256 ints
    int*   s_row = (int*)(smem + 3072);          // 128 ints
    int*   s_col = (int*)(smem + 3584);          // 256 ints
    if (tid < 128) {
        s_sqi[tid] = g_sq[bi + tid];
        s_ti[tid]  = tgt[bi + tid];
        s_row[tid] = 0x7f800000;
    }
    s_sqj[tid] = g_sq[bj + tid];
    s_tj[tid]  = tgt[bj + tid];
    s_col[tid] = 0x7f800000;
    __syncthreads();

    const int g4 = lane >> 2, i2 = lane & 3;
    float sqj_r[16]; int tj_r[16];
    #pragma unroll
    for (int blk = 0; blk < 8; blk++)
        #pragma unroll
        for (int e = 0; e < 2; e++) {
            int col = n0 + 8 * blk + 2 * i2 + e;
            sqj_r[blk * 2 + e] = s_sqj[col];
            tj_r[blk * 2 + e]  = s_tj[col];
        }

    #pragma unroll
    for (int mb = 0; mb < 4; mb++) {
        #pragma unroll
        for (int rh = 0; rh < 2; rh++) {
            int row = m0 + 16 * mb + g4 + 8 * rh;
            int grow = bi + row;
            float sqi = s_sqi[row];
            int   ti  = s_ti[row];
            #pragma unroll
            for (int blk = 0; blk < 8; blk++) {
                float2 v;
                #pragma unroll
                for (int e = 0; e < 2; e++) {
                    int q = rh * 2 + e;
                    float d2 = fmaf(-2.f, acc[mb][blk][q], sqi + sqj_r[blk * 2 + e]);
                    d2 = fmaxf(d2, 1e-12f);
                    if (ti == tj_r[blk * 2 + e]) d2 = __int_as_float(0x7f800000);
                    acc[mb][blk][q] = d2;
                    (&v.x)[e] = d2;
                }
                int gcol = bj + n0 + 8 * blk + 2 * i2;
                *(float2*)&g_dist2[(size_t)grow * N + gcol] = v;
                g_dist2[(size_t)gcol * N + grow] = v.x;
                g_dist2[(size_t)(gcol + 1) * N + grow] = v.y;
            }
        }
    }
    // row mins
    #pragma unroll
    for (int mb = 0; mb < 4; mb++)
        #pragma unroll
        for (int rh = 0; rh < 2; rh++) {
            float rm = __int_as_float(0x7f800000);
            #pragma unroll
            for (int blk = 0; blk < 8; blk++)
                #pragma unroll
                for (int e = 0; e < 2; e++) rm = fminf(rm, acc[mb][blk][rh * 2 + e]);
            rm = fminf(rm, __shfl_xor_sync(0xffffffffu, rm, 1));
            rm = fminf(rm, __shfl_xor_sync(0xffffffffu, rm, 2));
            if (i2 == 0) atomicMin(&s_row[m0 + 16 * mb + g4 + 8 * rh], __float_as_int(rm));
        }
    // col mins
    #pragma unroll
    for (int blk = 0; blk < 8; blk++)
        #pragma unroll
        for (int e = 0; e < 2; e++) {
            float cm = __int_as_float(0x7f800000);
            #pragma unroll
            for (int mb = 0; mb < 4; mb++)
                #pragma unroll
                for (int q = 0; q < 4; q += 2) cm = fminf(cm, acc[mb][blk][q + e]);
            cm = fminf(cm, __shfl_xor_sync(0xffffffffu, cm, 4));
            cm = fminf(cm, __shfl_xor_sync(0xffffffffu, cm, 8));
            cm = fminf(cm, __shfl_xor_sync(0xffffffffu, cm, 16));
            if (g4 == 0) atomicMin(&s_col[n0 + 8 * blk + 2 * i2 + e], __float_as_int(cm));
        }
    __syncthreads();
    if (tid < 128) atomicMin(&g_anA[bi + tid], s_row[tid]);
    atomicMin(&g_anA[bj + tid], s_col[tid]);
}

// ---------------- kernel 4: exact recheck of near-min candidates -----------
__global__ void recheck_kernel(const float* __restrict__ x) {
    __shared__ float xi[D];                      // 16KB
    __shared__ int   s_cnt;
    __shared__ int   s_list[1024];
    __shared__ float s_red[8];
    const int i = blockIdx.x, tid = threadIdx.x; // 256
    const int lane = tid & 31, wid = tid >> 5;

    if (tid == 0) s_cnt = 0;
    __syncthreads();
    const float thr = __int_as_float(g_anA[i]) + 12.0f;   // delta = 6, doubled
    const float* rowp = g_dist2 + (size_t)i * N;
    for (int k = tid; k < N; k += 256) {
        xi[k] = x[(size_t)i * D + k];
        float v = rowp[k];
        if (v <= thr) {
            int idx = atomicAdd(&s_cnt, 1);
            if (idx < 1024) s_list[idx] = k;
        }
    }
    __syncthreads();
    const int nc = min(s_cnt, 1024);
    const float sqi = g_sq[i];
    float best = INFINITY;
    for (int c = 0; c < nc; c++) {
        int j = s_list[c];
        const float* xj = x + (size_t)j * D;
        float p = 0.f;
        for (int k = tid; k < D; k += 256) p = fmaf(xi[k], xj[k], p);
        #pragma unroll
        for (int o = 16; o > 0; o >>= 1) p += __shfl_xor_sync(0xffffffffu, p, o);
        if (lane == 0) s_red[wid] = p;
        __syncthreads();
        if (tid == 0) {
            float dot = 0.f;
            #pragma unroll
            for (int w = 0; w < 8; w++) dot += s_red[w];
            float d2 = fmaxf(sqi + g_sq[j] - 2.f * dot, 1e-12f);
            best = fminf(best, d2);
        }
        __syncthreads();
    }
    if (tid == 0) g_an2f[i] = best;
}

// ---------------- kernel 5: deterministic finalize -------------------------
__global__ void finalize_kernel(float* __restrict__ out, int out_size) {
    const int tid = threadIdx.x;                 // 1024
    float trip = 0.f, prec = 0.f, stds = 0.f, xents = 0.f;
    for (int i = tid; i < N; i += 1024) {
        float ap = g_ap[i];
        float an = sqrtf(g_an2f[i]);
        trip += fmaxf(ap - an, 0.f);
        if (an > ap) prec += 1.f;
        stds += g_std[i];
        xents += g_xent[i];
    }
    __shared__ float s1[1024], s2[1024], s3[1024], s4[1024];
    s1[tid] = trip; s2[tid] = prec; s3[tid] = stds; s4[tid] = xents;
    __syncthreads();
    for (int off = 512; off > 0; off >>= 1) {
        if (tid < off) {
            s1[tid] += s1[tid + off]; s2[tid] += s2[tid + off];
            s3[tid] += s3[tid + off]; s4[tid] += s4[tid + off];
        }
        __syncthreads();
    }
    if (tid == 0) {
        float loss = (s1[0] / (float)N) + 0.5f * s3[0] + 0.5f * (s4[0] / (float)N);
        if (out_size >= 1) out[0] = loss;
        if (out_size >= 2) out[1] = s2[0] / (float)N;
    }
}

extern "C" void kernel_launch(void* const* d_in, const int* in_sizes, int n_in,
                              void* d_out, int out_size) {
    const float* x   = (const float*)d_in[0];
    const int*   tgt = (const int*)d_in[1];

    cudaFuncSetAttribute(gemm_min_mma, cudaFuncAttributeMaxDynamicSharedMemorySize, SMEM_TOTAL);

    row_stats_kernel<<<N, 256>>>(x, tgt);
    group_ap_kernel<<<N / 4, 128>>>(x);
    gemm_min_mma<<<272, 256, SMEM_TOTAL>>>(tgt);
    recheck_kernel<<<N, 256>>>(x);
    finalize_kernel<<<1, 1024>>>((float*)d_out, out_size);
}

// round 6
// speedup vs baseline: 8.2737x; 1.0354x over previous
#include <cuda_runtime.h>
#include <cuda_bf16.h>
#include <math.h>
#include <stdint.h>

#define N 4096
#define D 4096
#define CAP 256

// ---------------- scratch globals (no allocations allowed) -----------------
__device__ float g_sq[N];
__device__ float g_std[N];
__device__ float g_xent[N];
__device__ float g_ap[N];
__device__ int   g_anA[N];                    // approx min dist^2 (float bits)
__device__ float g_an2f[N];                   // exact min dist^2
__device__ int   g_ccnt[N];                   // candidate counts
__device__ int   g_cj[(size_t)N * CAP];       // candidate j-indices
__device__ float g_cv[(size_t)N * CAP];       // candidate approx d2
__device__ __nv_bfloat16 g_xhi[(size_t)N * D];

// ---------------- PTX helpers ----------------------------------------------
__device__ __forceinline__ uint32_t smem_u32(const void* p) {
    uint32_t a;
    asm("{ .reg .u64 t; cvta.to.shared.u64 t, %1; cvt.u32.u64 %0, t; }" : "=r"(a) : "l"(p));
    return a;
}
#define CP16(so, gp) asm volatile("cp.async.cg.shared.global [%0], [%1], 16;" :: "r"(so), "l"(gp) : "memory")
#define CP_COMMIT()  asm volatile("cp.async.commit_group;" ::: "memory")

__device__ __forceinline__ void ldsm4(uint32_t* r, uint32_t p) {
    asm volatile("ldmatrix.sync.aligned.m8n8.x4.shared.b16 {%0,%1,%2,%3}, [%4];"
                 : "=r"(r[0]), "=r"(r[1]), "=r"(r[2]), "=r"(r[3]) : "r"(p));
}
__device__ __forceinline__ void mma16816(float* d, const uint32_t* a, const uint32_t* b) {
    asm volatile("mma.sync.aligned.m16n8k16.row.col.f32.bf16.bf16.f32 "
                 "{%0,%1,%2,%3},{%4,%5,%6,%7},{%8,%9},{%0,%1,%2,%3};"
                 : "+f"(d[0]), "+f"(d[1]), "+f"(d[2]), "+f"(d[3])
                 : "r"(a[0]), "r"(a[1]), "r"(a[2]), "r"(a[3]), "r"(b[0]), "r"(b[1]));
}

// ---------------- kernel 1: fused row stats + intra-group dots + bf16 ------
// One block per group of 4 rows, 512 threads.
__global__ void __launch_bounds__(512)
stats_kernel(const float* __restrict__ x, const int* __restrict__ tgt) {
    const int g = blockIdx.x;
    const int tid = threadIdx.x, lane = tid & 31, w = tid >> 5;   // 16 warps
    const float* r = x + (size_t)(4 * g) * D;
    __nv_bfloat16* __restrict__ xh = g_xhi + (size_t)(4 * g) * D;

    float vals[18];
    #pragma unroll
    for (int q = 0; q < 18; q++) vals[q] = (q >= 8 && q < 12) ? -INFINITY : 0.f;

    for (int k = tid; k < D; k += 512) {
        float a = r[k], b = r[k + D], c = r[k + 2 * D], e = r[k + 3 * D];
        vals[0] += a; vals[1] += b; vals[2] += c; vals[3] += e;
        vals[4] = fmaf(a, a, vals[4]); vals[5] = fmaf(b, b, vals[5]);
        vals[6] = fmaf(c, c, vals[6]); vals[7] = fmaf(e, e, vals[7]);
        vals[8] = fmaxf(vals[8], a); vals[9] = fmaxf(vals[9], b);
        vals[10] = fmaxf(vals[10], c); vals[11] = fmaxf(vals[11], e);
        vals[12] = fmaf(a, b, vals[12]); vals[13] = fmaf(a, c, vals[13]);
        vals[14] = fmaf(a, e, vals[14]); vals[15] = fmaf(b, c, vals[15]);
        vals[16] = fmaf(b, e, vals[16]); vals[17] = fmaf(c, e, vals[17]);
        xh[k] = __float2bfloat16(a);
        xh[k + D] = __float2bfloat16(b);
        xh[k + 2 * D] = __float2bfloat16(c);
        xh[k + 3 * D] = __float2bfloat16(e);
    }
    __shared__ float red[18 * 16];
    #pragma unroll
    for (int q = 0; q < 18; q++) {
        float t = vals[q];
        const bool ismax = (q >= 8 && q < 12);
        #pragma unroll
        for (int o = 16; o > 0; o >>= 1) {
            float u = __shfl_xor_sync(0xffffffffu, t, o);
            t = ismax ? fmaxf(t, u) : (t + u);
        }
        if (lane == 0) red[q * 16 + w] = t;
    }
    __syncthreads();
    if (tid < 18) {
        float t = red[tid * 16];
        const bool ismax = (tid >= 8 && tid < 12);
        #pragma unroll
        for (int j = 1; j < 16; j++)
            t = ismax ? fmaxf(t, red[tid * 16 + j]) : (t + red[tid * 16 + j]);
        red[tid * 16] = t;
    }
    __syncthreads();
    float rm0 = red[8 * 16], rm1 = red[9 * 16], rm2 = red[10 * 16], rm3 = red[11 * 16];
    float ex[4] = {0.f, 0.f, 0.f, 0.f};
    for (int k = tid; k < D; k += 512) {
        ex[0] += __expf(r[k] - rm0);
        ex[1] += __expf(r[k + D] - rm1);
        ex[2] += __expf(r[k + 2 * D] - rm2);
        ex[3] += __expf(r[k + 3 * D] - rm3);
    }
    __shared__ float red2[4 * 16];
    #pragma unroll
    for (int q = 0; q < 4; q++) {
        float t = ex[q];
        #pragma unroll
        for (int o = 16; o > 0; o >>= 1) t += __shfl_xor_sync(0xffffffffu, t, o);
        if (lane == 0) red2[q * 16 + w] = t;
    }
    __syncthreads();
    if (tid < 4) {
        const int row = 4 * g + tid;
        float sum = red[tid * 16], ss = red[(4 + tid) * 16];
        float rm = red[(8 + tid) * 16];
        float se = 0.f;
        #pragma unroll
        for (int j = 0; j < 16; j++) se += red2[tid * 16 + j];
        g_sq[row] = ss;
        float var = (ss - sum * sum / (float)D) / (float)(D - 1);
        g_std[row] = sqrtf(fmaxf(var, 0.f));
        g_xent[row] = rm + logf(se) - x[(size_t)row * D + tgt[row]];
        g_anA[row] = 0x7f800000;
        g_ccnt[row] = 0;
        // hardest positive
        float sq0 = red[4 * 16], sq1 = red[5 * 16], sq2 = red[6 * 16], sq3 = red[7 * 16];
        float sqv[4] = {sq0, sq1, sq2, sq3};
        float dot[4][4];
        dot[0][1] = dot[1][0] = red[12 * 16];
        dot[0][2] = dot[2][0] = red[13 * 16];
        dot[0][3] = dot[3][0] = red[14 * 16];
        dot[1][2] = dot[2][1] = red[15 * 16];
        dot[1][3] = dot[3][1] = red[16 * 16];
        dot[2][3] = dot[3][2] = red[17 * 16];
        float ap = 1e-6f;
        #pragma unroll
        for (int b = 0; b < 4; b++) {
            if (b != tid) {
                float d2 = fmaxf(sqv[tid] + sqv[b] - 2.f * dot[tid][b], 1e-12f);
                ap = fmaxf(ap, sqrtf(d2));
            }
        }
        g_ap[row] = ap;
    }
}

// ---------------- kernel 2: hi bf16 Gram + min mining + candidate emit -----
// Tile 128(A) x 256(B), supra-diagonal only. 8 warps (2x4), warp 64x64.
#define RSTRB 80
#define A_HI  0
#define B_HI  10240
#define STG   30720
#define NSTG  4
#define SMEM_TOTAL (NSTG * STG)

struct TilePos { int bi, bj; };
__device__ __forceinline__ TilePos tile_pos(int t) {
    int rb = 0;
    for (;;) { int cnt = 16 - (rb >> 1); if (t < cnt) break; t -= cnt; rb++; }
    return { rb * 128, ((rb >> 1) + t) * 256 };
}

__device__ __forceinline__ void load_chunk(uint32_t su, int bi, int bj, int c, int lr2, int lu2) {
    const size_t kof = ((size_t)c << 5) + ((size_t)lu2 << 4);
    {
        int r = lr2;
        size_t go = ((size_t)(bi + r) << 12) + kof;
        uint32_t so = su + A_HI + r * RSTRB + lu2 * 32;
        CP16(so, g_xhi + go);
        CP16(so + 16, g_xhi + go + 8);
    }
    #pragma unroll
    for (int p = 0; p < 2; p++) {
        int r = lr2 + 128 * p;
        size_t go = ((size_t)(bj + r) << 12) + kof;
        uint32_t so = su + B_HI + r * RSTRB + lu2 * 32;
        CP16(so, g_xhi + go);
        CP16(so + 16, g_xhi + go + 8);
    }
    CP_COMMIT();
}

__global__ void __launch_bounds__(256, 1)
gemm_min_mma(const int* __restrict__ tgt) {
    extern __shared__ char smem[];
    const uint32_t sb = smem_u32(smem);
    const int tid = threadIdx.x, wid = tid >> 5, lane = tid & 31;
    TilePos tp = tile_pos(blockIdx.x);
    const int bi = tp.bi, bj = tp.bj;
    const int wr = wid >> 2, wc = wid & 3;
    const int m0 = wr * 64, n0 = wc * 64;

    float acc[4][8][4];
    #pragma unroll
    for (int a = 0; a < 4; a++)
        #pragma unroll
        for (int b = 0; b < 8; b++)
            #pragma unroll
            for (int q = 0; q < 4; q++) acc[a][b][q] = 0.f;

    const int lr2 = tid >> 1, lu2 = tid & 1;
    load_chunk(sb + 0 * STG, bi, bj, 0, lr2, lu2);
    load_chunk(sb + 1 * STG, bi, bj, 1, lr2, lu2);
    load_chunk(sb + 2 * STG, bi, bj, 2, lr2, lu2);

    const uint32_t a_base = A_HI + (uint32_t)(m0 + (lane & 15)) * RSTRB + (((lane >> 4) << 3) << 1);
    const uint32_t b_base = B_HI + (uint32_t)(n0 + (lane & 7) + ((lane >> 4) << 3)) * RSTRB
                          + ((((lane >> 3) & 1) << 3) << 1);

    for (int c = 0; c < 128; c++) {
        const uint32_t su = sb + (c & (NSTG - 1)) * STG;
        if (c < 126) asm volatile("cp.async.wait_group 2;" ::: "memory");
        else if (c == 126) asm volatile("cp.async.wait_group 1;" ::: "memory");
        else asm volatile("cp.async.wait_group 0;" ::: "memory");
        __syncthreads();

        #pragma unroll
        for (int kk = 0; kk < 2; kk++) {
            const uint32_t ko = kk * 32;
            uint32_t ah[4][4];
            #pragma unroll
            for (int mb = 0; mb < 4; mb++) ldsm4(ah[mb], su + a_base + ko + mb * 16 * RSTRB);
            #pragma unroll
            for (int g = 0; g < 4; g++) {
                uint32_t bh[4];
                ldsm4(bh, su + b_base + ko + g * 16 * RSTRB);
                #pragma unroll
                for (int mb = 0; mb < 4; mb++) {
                    mma16816(acc[mb][2 * g],     ah[mb], bh);
                    mma16816(acc[mb][2 * g + 1], ah[mb], bh + 2);
                }
            }
        }
        if (c + 3 < 128) load_chunk(sb + ((c + 3) & (NSTG - 1)) * STG, bi, bj, c + 3, lr2, lu2);
    }
    __syncthreads();

    // ---- epilogue: d2 + mask, tile row/col mins, candidate emission -------
    float* s_sqi = (float*)(smem);               // 128 floats
    float* s_sqj = (float*)(smem + 512);         // 256 floats
    int*   s_ti  = (int*)(smem + 1536);          // 128 ints
    int*   s_tj  = (int*)(smem + 2048);          // 256 ints
    int*   s_row = (int*)(smem + 3072);          // 128 ints
    int*   s_col = (int*)(smem + 3584);          // 256 ints
    if (tid < 128) {
        s_sqi[tid] = g_sq[bi + tid];
        s_ti[tid]  = tgt[bi + tid];
        s_row[tid] = 0x7f800000;
    }
    s_sqj[tid] = g_sq[bj + tid];
    s_tj[tid]  = tgt[bj + tid];
    s_col[tid] = 0x7f800000;
    __syncthreads();

    const int g4 = lane >> 2, i2 = lane & 3;
    float sqj_r[16]; int tj_r[16];
    #pragma unroll
    for (int blk = 0; blk < 8; blk++)
        #pragma unroll
        for (int e = 0; e < 2; e++) {
            int col = n0 + 8 * blk + 2 * i2 + e;
            sqj_r[blk * 2 + e] = s_sqj[col];
            tj_r[blk * 2 + e]  = s_tj[col];
        }

    #pragma unroll
    for (int mb = 0; mb < 4; mb++)
        #pragma unroll
        for (int rh = 0; rh < 2; rh++) {
            int row = m0 + 16 * mb + g4 + 8 * rh;
            float sqi = s_sqi[row];
            int   ti  = s_ti[row];
            #pragma unroll
            for (int blk = 0; blk < 8; blk++)
                #pragma unroll
                for (int e = 0; e < 2; e++) {
                    int q = rh * 2 + e;
                    float d2 = fmaf(-2.f, acc[mb][blk][q], sqi + sqj_r[blk * 2 + e]);
                    d2 = fmaxf(d2, 1e-12f);
                    if (ti == tj_r[blk * 2 + e]) d2 = __int_as_float(0x7f800000);
                    acc[mb][blk][q] = d2;
                }
        }
    // tile row mins
    #pragma unroll
    for (int mb = 0; mb < 4; mb++)
        #pragma unroll
        for (int rh = 0; rh < 2; rh++) {
            float rm = __int_as_float(0x7f800000);
            #pragma unroll
            for (int blk = 0; blk < 8; blk++)
                #pragma unroll
                for (int e = 0; e < 2; e++) rm = fminf(rm, acc[mb][blk][rh * 2 + e]);
            rm = fminf(rm, __shfl_xor_sync(0xffffffffu, rm, 1));
            rm = fminf(rm, __shfl_xor_sync(0xffffffffu, rm, 2));
            if (i2 == 0) atomicMin(&s_row[m0 + 16 * mb + g4 + 8 * rh], __float_as_int(rm));
        }
    // tile col mins
    #pragma unroll
    for (int blk = 0; blk < 8; blk++)
        #pragma unroll
        for (int e = 0; e < 2; e++) {
            float cm = __int_as_float(0x7f800000);
            #pragma unroll
            for (int mb = 0; mb < 4; mb++)
                #pragma unroll
                for (int q = 0; q < 4; q += 2) cm = fminf(cm, acc[mb][blk][q + e]);
            cm = fminf(cm, __shfl_xor_sync(0xffffffffu, cm, 4));
            cm = fminf(cm, __shfl_xor_sync(0xffffffffu, cm, 8));
            cm = fminf(cm, __shfl_xor_sync(0xffffffffu, cm, 16));
            if (g4 == 0) atomicMin(&s_col[n0 + 8 * blk + 2 * i2 + e], __float_as_int(cm));
        }
    __syncthreads();
    // global approx mins
    if (tid < 128) atomicMin(&g_anA[bi + tid], s_row[tid]);
    atomicMin(&g_anA[bj + tid], s_col[tid]);
    // candidate emission vs tile-local thresholds
    #pragma unroll
    for (int mb = 0; mb < 4; mb++)
        #pragma unroll
        for (int rh = 0; rh < 2; rh++) {
            int row = m0 + 16 * mb + g4 + 8 * rh;
            float thrR = __int_as_float(s_row[row]) + 12.f;
            #pragma unroll
            for (int blk = 0; blk < 8; blk++)
                #pragma unroll
                for (int e = 0; e < 2; e++) {
                    int col = n0 + 8 * blk + 2 * i2 + e;
                    float val = acc[mb][blk][rh * 2 + e];
                    if (val <= thrR) {
                        int gi = bi + row;
                        int idx = atomicAdd(&g_ccnt[gi], 1);
                        if (idx < CAP) { g_cj[(size_t)gi * CAP + idx] = bj + col; g_cv[(size_t)gi * CAP + idx] = val; }
                    }
                    if (val <= __int_as_float(s_col[col]) + 12.f) {
                        int gj = bj + col;
                        int idx = atomicAdd(&g_ccnt[gj], 1);
                        if (idx < CAP) { g_cj[(size_t)gj * CAP + idx] = bi + row; g_cv[(size_t)gj * CAP + idx] = val; }
                    }
                }
        }
}

// ---------------- kernel 3: exact fp32 recheck of surviving candidates -----
__global__ void recheck_kernel(const float* __restrict__ x) {
    __shared__ float xi[D];                      // 16KB
    __shared__ int s_j[64];
    __shared__ int s_n;
    __shared__ float s_red[8];
    const int i = blockIdx.x, tid = threadIdx.x; // 256
    const int lane = tid & 31, w = tid >> 5;

    if (tid == 0) s_n = 0;
    __syncthreads();
    const float thr = __int_as_float(g_anA[i]) + 12.0f;
    const int cnt = min(g_ccnt[i], CAP);
    for (int c = tid; c < cnt; c += 256) {
        if (g_cv[(size_t)i * CAP + c] <= thr) {
            int idx = atomicAdd(&s_n, 1);
            if (idx < 64) s_j[idx] = g_cj[(size_t)i * CAP + c];
        }
    }
    const float4* xr4 = (const float4*)(x + (size_t)i * D);
    for (int k = tid; k < D / 4; k += 256) ((float4*)xi)[k] = xr4[k];
    __syncthreads();
    const int nc = min(s_n, 64);
    const float sqi = g_sq[i];
    float best = INFINITY;
    for (int c = 0; c < nc; c++) {
        int j = s_j[c];
        const float4* xj4 = (const float4*)(x + (size_t)j * D);
        float p = 0.f;
        for (int k = tid; k < D / 4; k += 256) {
            float4 a = ((const float4*)xi)[k];
            float4 b = __ldg(xj4 + k);
            p = fmaf(a.x, b.x, p); p = fmaf(a.y, b.y, p);
            p = fmaf(a.z, b.z, p); p = fmaf(a.w, b.w, p);
        }
        #pragma unroll
        for (int o = 16; o > 0; o >>= 1) p += __shfl_xor_sync(0xffffffffu, p, o);
        if (lane == 0) s_red[w] = p;
        __syncthreads();
        if (tid == 0) {
            float dot = 0.f;
            #pragma unroll
            for (int q = 0; q < 8; q++) dot += s_red[q];
            float d2 = fmaxf(sqi + g_sq[j] - 2.f * dot, 1e-12f);
            best = fminf(best, d2);
        }
        __syncthreads();
    }
    if (tid == 0) g_an2f[i] = best;
}

// ---------------- kernel 4: deterministic finalize -------------------------
__global__ void finalize_kernel(float* __restrict__ out, int out_size) {
    const int tid = threadIdx.x;                 // 1024
    float trip = 0.f, prec = 0.f, stds = 0.f, xents = 0.f;
    for (int i = tid; i < N; i += 1024) {
        float ap = g_ap[i];
        float an = sqrtf(g_an2f[i]);
        trip += fmaxf(ap - an, 0.f);
        if (an > ap) prec += 1.f;
        stds += g_std[i];
        xents += g_xent[i];
    }
    __shared__ float s1[1024], s2[1024], s3[1024], s4[1024];
    s1[tid] = trip; s2[tid] = prec; s3[tid] = stds; s4[tid] = xents;
    __syncthreads();
    for (int off = 512; off > 0; off >>= 1) {
        if (tid < off) {
            s1[tid] += s1[tid + off]; s2[tid] += s2[tid + off];
            s3[tid] += s3[tid + off]; s4[tid] += s4[tid + off];
        }
        __syncthreads();
    }
    if (tid == 0) {
        float loss = (s1[0] / (float)N) + 0.5f * s3[0] + 0.5f * (s4[0] / (float)N);
        if (out_size >= 1) out[0] = loss;
        if (out_size >= 2) out[1] = s2[0] / (float)N;
    }
}

extern "C" void kernel_launch(void* const* d_in, const int* in_sizes, int n_in,
                              void* d_out, int out_size) {
    const float* x   = (const float*)d_in[0];
    const int*   tgt = (const int*)d_in[1];

    cudaFuncSetAttribute(gemm_min_mma, cudaFuncAttributeMaxDynamicSharedMemorySize, SMEM_TOTAL);

    stats_kernel<<<N / 4, 512>>>(x, tgt);
    gemm_min_mma<<<272, 256, SMEM_TOTAL>>>(tgt);
    recheck_kernel<<<N, 256>>>(x);
    finalize_kernel<<<1, 1024>>>((float*)d_out, out_size);
}